// round 15
// baseline (speedup 1.0000x reference)
#include <cuda_runtime.h>
#include <cuda_fp16.h>
#include <cstdint>

// ---------------- Problem constants ----------------
#define E_TOTAL   500000
#define TILE_M    128
#define NTILES    ((E_TOTAL + TILE_M - 1) / TILE_M)   // 3907
#define NTHREADS  256

// SMEM: 3 A-chunk buffers [128 rows x 64 halfs] = 16KB each -> 48KB, 2 CTAs/SM
#define SMEM_TOTAL (3 * 16384)

// Repacked fp16 W in B-fragment order:
// idx = (((c*2 + wn)*4 + nf)*2 + tp)*32 + lane; uint4 = b-regs for steps 2tp,2tp+1.
__device__ uint4 WrepH[2560];   // 40KB

// ---------------- helpers ----------------
__device__ __forceinline__ uint32_t smem_u32(const void* p) {
    uint32_t a;
    asm("{ .reg .u64 t; cvta.to.shared.u64 t, %1; cvt.u32.u64 %0, t; }"
        : "=r"(a) : "l"(p));
    return a;
}

__device__ __forceinline__ uint32_t f2h2(float a, float b) {
    __half2 h = __floats2half2_rn(a, b);
    return *reinterpret_cast<uint32_t*>(&h);
}

__device__ __forceinline__ uint32_t hmin2u(uint32_t a, uint32_t b) {
    __half2 r = __hmin2(*reinterpret_cast<__half2*>(&a),
                        *reinterpret_cast<__half2*>(&b));
    return *reinterpret_cast<uint32_t*>(&r);
}

__device__ __forceinline__ uint32_t hmax2u(uint32_t a, uint32_t b) {
    __half2 r = __hmax2(*reinterpret_cast<__half2*>(&a),
                        *reinterpret_cast<__half2*>(&b));
    return *reinterpret_cast<uint32_t*>(&r);
}

// A-chunk layout: row-major fp16, 128B per row (64 halfs), 16B-group swizzle:
// group position p (0..7) stored at p ^ (row & 7).
// Producer 8B-slot address (slot q = cols 4q..4q+3):
__device__ __forceinline__ uint32_t arow_off(int row, int q) {
    return (uint32_t)(row * 128 + (((q >> 1) ^ (row & 7)) << 4) + ((q & 1) << 3));
}

__device__ __forceinline__ void sts64(uint32_t addr, uint32_t a, uint32_t b) {
    asm volatile("st.shared.v2.b32 [%0], {%1,%2};"
                 :: "r"(addr), "r"(a), "r"(b) : "memory");
}

// ldmatrix x4 (b16): canonical A m16k16 fragment load.
__device__ __forceinline__ void ldsm_x4(uint32_t* r, uint32_t addr) {
    asm volatile("ldmatrix.sync.aligned.m8n8.x4.shared.b16 {%0,%1,%2,%3}, [%4];"
                 : "=r"(r[0]), "=r"(r[1]), "=r"(r[2]), "=r"(r[3])
                 : "r"(addr));
}

// m16n8k16 fp16 mma, fp32 accum: D = A*B + D
__device__ __forceinline__ void mma_f16(float* c, const uint32_t* a, uint32_t b0,
                                        uint32_t b1) {
    asm volatile(
        "mma.sync.aligned.m16n8k16.row.col.f32.f16.f16.f32 "
        "{%0,%1,%2,%3},{%4,%5,%6,%7},{%8,%9},{%0,%1,%2,%3};"
        : "+f"(c[0]), "+f"(c[1]), "+f"(c[2]), "+f"(c[3])
        : "r"(a[0]), "r"(a[1]), "r"(a[2]), "r"(a[3]), "r"(b0), "r"(b1));
}

// ---------------- W repack kernel (runs once, tiny) ----------------
__global__ void repack_w_h(const float* __restrict__ W) {
    int idx = blockIdx.x * blockDim.x + threadIdx.x;
    if (idx >= 2560) return;
    int lane = idx & 31;
    int tp   = (idx >> 5) & 1;
    int nf   = (idx >> 6) & 3;
    int wn   = (idx >> 8) & 1;
    int c    = idx >> 9;
    int g    = lane >> 2, tig = lane & 3;
    int n    = wn * 32 + nf * 8 + g;
    const float* wr = W + (size_t)n * 320;
    int kA = c * 64 + (2 * tp) * 16 + 2 * tig;
    int kB = kA + 16;
    uint4 v;
    v.x = f2h2(wr[kA], wr[kA + 1]);
    v.y = f2h2(wr[kA + 8], wr[kA + 9]);
    v.z = f2h2(wr[kB], wr[kB + 1]);
    v.w = f2h2(wr[kB + 8], wr[kB + 9]);
    WrepH[idx] = v;
}

// ---------------- consumer: half-chunk (k32) of MMA, warp tile m32 x n32 ----
// h selects t = 2h, 2h+1. B loaded per-half (16 transient regs).
__device__ __forceinline__ void mma_half(uint32_t aB, const uint4* wrc, int wm,
                                         int lid, int h, float acc[2][4][4]) {
    uint4 Bq[4];
#pragma unroll
    for (int nf = 0; nf < 4; nf++)
        Bq[nf] = __ldg(wrc + (nf * 2 + h) * 32);

    const int arow = lid & 15;
    const int ksel = lid >> 4;
#pragma unroll
    for (int tl = 0; tl < 2; tl++) {
        const int t  = 2 * h + tl;
        const int kb = 2 * t + ksel;
        uint32_t Af[2][4];
#pragma unroll
        for (int mb = 0; mb < 2; mb++) {
            int row = wm * 32 + mb * 16 + arow;
            ldsm_x4(Af[mb], aB + (uint32_t)(row * 128 + ((kb ^ (row & 7)) << 4)));
        }
#pragma unroll
        for (int mb = 0; mb < 2; mb++)
#pragma unroll
            for (int nf = 0; nf < 4; nf++) {
                uint32_t b0 = tl ? Bq[nf].z : Bq[nf].x;
                uint32_t b1 = tl ? Bq[nf].w : Bq[nf].y;
                mma_f16(acc[mb][nf], Af[mb], b0, b1);
            }
    }
}

// ---------------- producer pieces ----------------
// Warp owns 16 edges. Lane: q = lid&15 (8B col-slot), half = lid>>4.
// Iteration i covers edge l = 2i + half. Gathers split in halves of 4 iters.

// Load 4 iterations of a neighbor pair (i0..i0+3) into VA/VB (32 regs).
__device__ __forceinline__ void pair_load4(const float* __restrict__ x, int cA,
                                           int cB, int q, int half, int i0,
                                           float4* VA, float4* VB) {
#pragma unroll
    for (int j = 0; j < 4; j++) {
        int l  = 2 * (i0 + j) + half;
        int ia = __shfl_sync(0xffffffffu, cA, l);
        int ib = __shfl_sync(0xffffffffu, cB, l);
        float4 va = make_float4(0.f, 0.f, 0.f, 0.f);
        float4 vb = make_float4(0.f, 0.f, 0.f, 0.f);
        if (ia >= 0) va = __ldg((const float4*)x + (size_t)ia * 16 + q);
        if (ib >= 0) vb = __ldg((const float4*)x + (size_t)ib * 16 + q);
        VA[j] = va;
        VB[j] = vb;
    }
}

// Convert to fp16, min/max in half2, STS min, hold packed max.
__device__ __forceinline__ void pair_proc4(uint32_t bufMin, int we0, int q,
                                           int half, int i0, const float4* VA,
                                           const float4* VB, uint2* MXh) {
#pragma unroll
    for (int j = 0; j < 4; j++) {
        int l = 2 * (i0 + j) + half;
        uint32_t a0 = f2h2(VA[j].x, VA[j].y), a1 = f2h2(VA[j].z, VA[j].w);
        uint32_t b0 = f2h2(VB[j].x, VB[j].y), b1 = f2h2(VB[j].z, VB[j].w);
        sts64(bufMin + arow_off(we0 + l, q), hmin2u(a0, b0), hmin2u(a1, b1));
        MXh[j] = make_uint2(hmax2u(a0, b0), hmax2u(a1, b1));
    }
}

__device__ __forceinline__ void sts_maxh(uint32_t buf, int we0, int q, int half,
                                         const uint2* MXh) {
#pragma unroll
    for (int i = 0; i < 8; i++) {
        int l = 2 * i + half;
        sts64(buf + arow_off(we0 + l, q), MXh[i].x, MXh[i].y);
    }
}

__device__ __forceinline__ void x_load4(const float* __restrict__ x, int basew,
                                        int q, int half, int i0, float4* V) {
#pragma unroll
    for (int j = 0; j < 4; j++) {
        int e = basew + 2 * (i0 + j) + half;
        if (e > E_TOTAL - 1) e = E_TOTAL - 1;
        V[j] = __ldg((const float4*)x + (size_t)e * 16 + q);
    }
}

__device__ __forceinline__ void x_proc4(uint32_t buf, int we0, int q, int half,
                                        int i0, const float4* V) {
#pragma unroll
    for (int j = 0; j < 4; j++) {
        int l = 2 * (i0 + j) + half;
        sts64(buf + arow_off(we0 + l, q), f2h2(V[j].x, V[j].y),
              f2h2(V[j].z, V[j].w));
    }
}

// ---------------- main kernel ----------------
// K=320 chunks: c0:x c1:min01 c2:max01 c3:min23 c4:max23
// TILE_M=128, 256 thr, 2 CTAs/SM (48KB smem). Uniform warps:
// producer warp owns 16 edges; consumer m32 x n32 (4m x 2n).
// 3-buffer ring, 5 phases. Within gather phases, loads are issued in
// half-batches with an independent mma_half between issue and use.
__global__ void __launch_bounds__(NTHREADS, 2)
meshconv_kernel(const float* __restrict__ x, const int* __restrict__ nbr,
                const float* __restrict__ bias, float* __restrict__ out) {
    extern __shared__ char smem[];
    const uint32_t sb = smem_u32(smem);
    const int tid = threadIdx.x;
    const int lid = tid & 31, wid = tid >> 5;
    // consumer identity
    const int wm = wid & 3, wn = wid >> 2;
    const int g = lid >> 2, tig = lid & 3;
    // producer identity
    const int q = lid & 15, half = lid >> 4;
    const int we0 = wid * 16;

    // bias fragment (accumulator init values)
    float bv[4][2];
#pragma unroll
    for (int nf = 0; nf < 4; nf++) {
        int bc = wn * 32 + nf * 8 + tig * 2;
        bv[nf][0] = __ldg(bias + bc);
        bv[nf][1] = __ldg(bias + bc + 1);
    }

    const uint4* wrbase = WrepH + wn * 256 + lid;   // + c*512 per chunk

    // ---- prologue: NB + stage c0 of first tile into buf 0 ----
    int tile = blockIdx.x;
    int NBx, NBy, NBz, NBw;
    {
        int e = tile * TILE_M + we0 + (lid & 15);
        if (e > E_TOTAL - 1) e = E_TOTAL - 1;
        int4 v = __ldg((const int4*)nbr + e);
        NBx = v.x; NBy = v.y; NBz = v.z; NBw = v.w;
    }
    {
        float4 V[4];
        x_load4(x, tile * TILE_M + we0, q, half, 0, V);
        x_proc4(sb, we0, q, half, 0, V);
        x_load4(x, tile * TILE_M + we0, q, half, 4, V);
        x_proc4(sb, we0, q, half, 4, V);
    }
    __syncthreads();

    int bc3 = 0;   // buffer rotation: buf(j) = (bc3 + j) % 3
    for (; tile < NTILES; tile += gridDim.x) {
        int tn = tile + gridDim.x;
        if (tn >= NTILES) tn = tile;
        const int nbase = tn * TILE_M + we0;
        const int tbase = tile * TILE_M;

        const int u1 = (bc3 + 1 == 3) ? 0 : bc3 + 1;
        const int u2 = (u1 + 1 == 3) ? 0 : u1 + 1;
        const uint32_t b_c0 = sb + (uint32_t)bc3 * 16384u;   // c0, c3
        const uint32_t b_c1 = sb + (uint32_t)u1 * 16384u;    // c1, c4
        const uint32_t b_c2 = sb + (uint32_t)u2 * 16384u;    // c2, next c0

        float acc[2][4][4];
#pragma unroll
        for (int mb = 0; mb < 2; mb++)
#pragma unroll
            for (int nf = 0; nf < 4; nf++) {
                acc[mb][nf][0] = bv[nf][0];
                acc[mb][nf][1] = bv[nf][1];
                acc[mb][nf][2] = bv[nf][0];
                acc[mb][nf][3] = bv[nf][1];
            }

        uint2 MXh[8];    // held packed max stream (16 regs)
        float4 VA[4], VB[4];

        // ---- s0: pair0 gathers interleaved with mma c0(b_c0); min01 -> b_c1
        pair_load4(x, NBx, NBy, q, half, 0, VA, VB);
        mma_half(b_c0, wrbase + 0 * 512, wm, lid, 0, acc);
        pair_proc4(b_c1, we0, q, half, 0, VA, VB, MXh + 0);
        pair_load4(x, NBx, NBy, q, half, 4, VA, VB);
        mma_half(b_c0, wrbase + 0 * 512, wm, lid, 1, acc);
        pair_proc4(b_c1, we0, q, half, 4, VA, VB, MXh + 4);
        __syncthreads();

        // ---- s1: STS max01 -> b_c2; pair1 gathers + mma c1(b_c1); min23 -> b_c0
        sts_maxh(b_c2, we0, q, half, MXh);
        pair_load4(x, NBz, NBw, q, half, 0, VA, VB);
        mma_half(b_c1, wrbase + 1 * 512, wm, lid, 0, acc);
        pair_proc4(b_c0, we0, q, half, 0, VA, VB, MXh + 0);
        pair_load4(x, NBz, NBw, q, half, 4, VA, VB);
        mma_half(b_c1, wrbase + 1 * 512, wm, lid, 1, acc);
        pair_proc4(b_c0, we0, q, half, 4, VA, VB, MXh + 4);
        __syncthreads();

        // ---- s2: STS max23 -> b_c1; prefetch next NB; mma c2(b_c2)
        sts_maxh(b_c1, we0, q, half, MXh);
        int NBnx, NBny, NBnz, NBnw;
        {
            int e = nbase + (lid & 15);
            if (e > E_TOTAL - 1) e = E_TOTAL - 1;
            int4 v = __ldg((const int4*)nbr + e);
            NBnx = v.x; NBny = v.y; NBnz = v.z; NBnw = v.w;
        }
        mma_half(b_c2, wrbase + 2 * 512, wm, lid, 0, acc);
        mma_half(b_c2, wrbase + 2 * 512, wm, lid, 1, acc);
        __syncthreads();

        // ---- s3: stage next tile's c0 -> b_c2, interleaved with mma c3(b_c0)
        x_load4(x, nbase, q, half, 0, VA);
        mma_half(b_c0, wrbase + 3 * 512, wm, lid, 0, acc);
        x_proc4(b_c2, we0, q, half, 0, VA);
        x_load4(x, nbase, q, half, 4, VA);
        mma_half(b_c0, wrbase + 3 * 512, wm, lid, 1, acc);
        x_proc4(b_c2, we0, q, half, 4, VA);
        __syncthreads();

        // ---- s4: mma c4(b_c1); rotate; epilogue (pure STG -> no sync needed)
        mma_half(b_c1, wrbase + 4 * 512, wm, lid, 0, acc);
        mma_half(b_c1, wrbase + 4 * 512, wm, lid, 1, acc);
        NBx = NBnx; NBy = NBny; NBz = NBnz; NBw = NBnw;
        bc3 = u2;

#pragma unroll
        for (int mb = 0; mb < 2; mb++) {
#pragma unroll
            for (int nf = 0; nf < 4; nf++) {
                const int e0  = tbase + wm * 32 + mb * 16 + g;
                const int e1  = e0 + 8;
                const int col = wn * 32 + nf * 8 + tig * 2;
                if (e0 < E_TOTAL)
                    *(float2*)(out + (size_t)e0 * 64 + col) =
                        make_float2(acc[mb][nf][0], acc[mb][nf][1]);
                if (e1 < E_TOTAL)
                    *(float2*)(out + (size_t)e1 * 64 + col) =
                        make_float2(acc[mb][nf][2], acc[mb][nf][3]);
            }
        }
    }
}

// ---------------- launch ----------------
extern "C" void kernel_launch(void* const* d_in, const int* in_sizes, int n_in,
                              void* d_out, int out_size) {
    const float* x   = (const float*)d_in[0];
    const int*   nbr = (const int*)d_in[1];
    const float* W   = (const float*)d_in[2];
    const float* b   = (const float*)d_in[3];
    float* out = (float*)d_out;

    int nsm = 0;
    cudaDeviceGetAttribute(&nsm, cudaDevAttrMultiProcessorCount, 0);
    if (nsm <= 0) nsm = 148;

    repack_w_h<<<10, 256>>>(W);

    cudaFuncSetAttribute(meshconv_kernel,
                         cudaFuncAttributeMaxDynamicSharedMemorySize, SMEM_TOTAL);
    meshconv_kernel<<<2 * nsm, NTHREADS, SMEM_TOTAL>>>(x, nbr, b, out);
}

// round 16
// speedup vs baseline: 1.1128x; 1.1128x over previous
#include <cuda_runtime.h>
#include <cuda_fp16.h>
#include <cstdint>

// ---------------- Problem constants ----------------
#define E_TOTAL   500000
#define TILE_M    128
#define NTILES    ((E_TOTAL + TILE_M - 1) / TILE_M)   // 3907
#define NTHREADS  256

// SMEM: 3 A-chunk buffers [128 rows x 64 halfs] = 16KB each -> 48KB, 2 CTAs/SM
#define SMEM_TOTAL (3 * 16384)

// fp16 copy of x: row e = 64 halfs = 128B = 8 uint4. 64MB, zero-init (bss).
__device__ uint4 XH[E_TOTAL * 8];

// Repacked fp16 W in B-fragment order:
// idx = (((c*2 + wn)*4 + nf)*2 + tp)*32 + lane; uint4 = b-regs for steps 2tp,2tp+1.
__device__ uint4 WrepH[2560];   // 40KB

// ---------------- helpers ----------------
__device__ __forceinline__ uint32_t smem_u32(const void* p) {
    uint32_t a;
    asm("{ .reg .u64 t; cvta.to.shared.u64 t, %1; cvt.u32.u64 %0, t; }"
        : "=r"(a) : "l"(p));
    return a;
}

__device__ __forceinline__ uint32_t f2h2(float a, float b) {
    __half2 h = __floats2half2_rn(a, b);
    return *reinterpret_cast<uint32_t*>(&h);
}

__device__ __forceinline__ uint32_t hmin2u(uint32_t a, uint32_t b) {
    __half2 r = __hmin2(*reinterpret_cast<__half2*>(&a),
                        *reinterpret_cast<__half2*>(&b));
    return *reinterpret_cast<uint32_t*>(&r);
}

__device__ __forceinline__ uint32_t hmax2u(uint32_t a, uint32_t b) {
    __half2 r = __hmax2(*reinterpret_cast<__half2*>(&a),
                        *reinterpret_cast<__half2*>(&b));
    return *reinterpret_cast<uint32_t*>(&r);
}

__device__ __forceinline__ uint4 hmin4(uint4 a, uint4 b) {
    return make_uint4(hmin2u(a.x, b.x), hmin2u(a.y, b.y),
                      hmin2u(a.z, b.z), hmin2u(a.w, b.w));
}

__device__ __forceinline__ uint4 hmax4(uint4 a, uint4 b) {
    return make_uint4(hmax2u(a.x, b.x), hmax2u(a.y, b.y),
                      hmax2u(a.z, b.z), hmax2u(a.w, b.w));
}

// A-chunk layout: row-major fp16, 128B/row (8 x 16B groups). Logical group g
// of row r stored at position g ^ (r & 7)  (16B-granular XOR swizzle).
__device__ __forceinline__ uint32_t aoff(int row, int g) {
    return (uint32_t)(row * 128 + ((g ^ (row & 7)) << 4));
}

__device__ __forceinline__ void sts128(uint32_t addr, uint4 v) {
    asm volatile("st.shared.v4.b32 [%0], {%1,%2,%3,%4};"
                 :: "r"(addr), "r"(v.x), "r"(v.y), "r"(v.z), "r"(v.w) : "memory");
}

// ldmatrix x4 (b16): canonical A m16k16 fragment load.
__device__ __forceinline__ void ldsm_x4(uint32_t* r, uint32_t addr) {
    asm volatile("ldmatrix.sync.aligned.m8n8.x4.shared.b16 {%0,%1,%2,%3}, [%4];"
                 : "=r"(r[0]), "=r"(r[1]), "=r"(r[2]), "=r"(r[3])
                 : "r"(addr));
}

// m16n8k16 fp16 mma, fp32 accum: D = A*B + D
__device__ __forceinline__ void mma_f16(float* c, const uint32_t* a, uint32_t b0,
                                        uint32_t b1) {
    asm volatile(
        "mma.sync.aligned.m16n8k16.row.col.f32.f16.f16.f32 "
        "{%0,%1,%2,%3},{%4,%5,%6,%7},{%8,%9},{%0,%1,%2,%3};"
        : "+f"(c[0]), "+f"(c[1]), "+f"(c[2]), "+f"(c[3])
        : "r"(a[0]), "r"(a[1]), "r"(a[2]), "r"(a[3]), "r"(b0), "r"(b1));
}

// ---------------- prep kernels (run once per launch, streaming) ----------------
__global__ void convert_x_kernel(const float4* __restrict__ x4) {
    size_t idx = (size_t)blockIdx.x * blockDim.x + threadIdx.x;
    if (idx >= (size_t)E_TOTAL * 8) return;
    float4 a = x4[2 * idx];
    float4 b = x4[2 * idx + 1];
    XH[idx] = make_uint4(f2h2(a.x, a.y), f2h2(a.z, a.w),
                         f2h2(b.x, b.y), f2h2(b.z, b.w));
}

__global__ void repack_w_h(const float* __restrict__ W) {
    int idx = blockIdx.x * blockDim.x + threadIdx.x;
    if (idx >= 2560) return;
    int lane = idx & 31;
    int tp   = (idx >> 5) & 1;
    int nf   = (idx >> 6) & 3;
    int wn   = (idx >> 8) & 1;
    int c    = idx >> 9;
    int g    = lane >> 2, tig = lane & 3;
    int n    = wn * 32 + nf * 8 + g;
    const float* wr = W + (size_t)n * 320;
    int kA = c * 64 + (2 * tp) * 16 + 2 * tig;
    int kB = kA + 16;
    uint4 v;
    v.x = f2h2(wr[kA], wr[kA + 1]);
    v.y = f2h2(wr[kA + 8], wr[kA + 9]);
    v.z = f2h2(wr[kB], wr[kB + 1]);
    v.w = f2h2(wr[kB + 8], wr[kB + 9]);
    WrepH[idx] = v;
}

// ---------------- consumer: half-chunk (k32) of MMA, warp tile m32 x n32 ----
// h selects t = 2h, 2h+1. B loaded per-half (16 transient regs).
__device__ __forceinline__ void mma_half(uint32_t aB, const uint4* wrc, int wm,
                                         int lid, int h, float acc[2][4][4]) {
    uint4 Bq[4];
#pragma unroll
    for (int nf = 0; nf < 4; nf++)
        Bq[nf] = __ldg(wrc + (nf * 2 + h) * 32);

    const int arow = lid & 15;
    const int ksel = lid >> 4;
#pragma unroll
    for (int tl = 0; tl < 2; tl++) {
        const int t  = 2 * h + tl;
        const int kb = 2 * t + ksel;
        uint32_t Af[2][4];
#pragma unroll
        for (int mb = 0; mb < 2; mb++) {
            int row = wm * 32 + mb * 16 + arow;
            ldsm_x4(Af[mb], aB + aoff(row, kb));
        }
#pragma unroll
        for (int mb = 0; mb < 2; mb++)
#pragma unroll
            for (int nf = 0; nf < 4; nf++) {
                uint32_t b0 = tl ? Bq[nf].z : Bq[nf].x;
                uint32_t b1 = tl ? Bq[nf].w : Bq[nf].y;
                mma_f16(acc[mb][nf], Af[mb], b0, b1);
            }
    }
}

// ---------------- producer pieces ----------------
// Warp owns 16 edges. Lane: eo = lid>>3 (0..3), cs = lid&7 (16B group slot).
// Stream instruction i (0..3) covers edge l = 4*i + eo; lane loads/stores the
// full 16B group cs of that row (fp16 row = 128B = 8 groups).

// Load 2 stream instructions (i0, i0+1) of a neighbor pair. comp on lanes 0..15.
__device__ __forceinline__ void pair_load2(int cA, int cB, int i0, int eo,
                                           int cs, uint4* VA, uint4* VB) {
#pragma unroll
    for (int j = 0; j < 2; j++) {
        int l  = 4 * (i0 + j) + eo;
        int ia = __shfl_sync(0xffffffffu, cA, l);
        int ib = __shfl_sync(0xffffffffu, cB, l);
        VA[j] = (ia >= 0) ? __ldg(XH + (size_t)ia * 8 + cs)
                          : make_uint4(0, 0, 0, 0);
        VB[j] = (ib >= 0) ? __ldg(XH + (size_t)ib * 8 + cs)
                          : make_uint4(0, 0, 0, 0);
    }
}

// min -> STS into bufMin; max held in MX[i0..i0+1].
__device__ __forceinline__ void pair_proc2(uint32_t bufMin, int we0, int i0,
                                           int eo, int cs, const uint4* VA,
                                           const uint4* VB, uint4* MX) {
#pragma unroll
    for (int j = 0; j < 2; j++) {
        int r = we0 + 4 * (i0 + j) + eo;
        sts128(bufMin + aoff(r, cs), hmin4(VA[j], VB[j]));
        MX[i0 + j] = hmax4(VA[j], VB[j]);
    }
}

// Full held-stream STS (4 instructions).
__device__ __forceinline__ void sts_stream(uint32_t buf, int we0, int eo,
                                           int cs, const uint4* V) {
#pragma unroll
    for (int i = 0; i < 4; i++) {
        int r = we0 + 4 * i + eo;
        sts128(buf + aoff(r, cs), V[i]);
    }
}

// Own-row x stream load (coalesced; 4 LDG.128).
__device__ __forceinline__ void x_load4(int basew, int eo, int cs, uint4* V) {
#pragma unroll
    for (int i = 0; i < 4; i++) {
        int e = basew + 4 * i + eo;
        if (e > E_TOTAL - 1) e = E_TOTAL - 1;
        V[i] = __ldg(XH + (size_t)e * 8 + cs);
    }
}

// ---------------- main kernel ----------------
// K=320 chunks: c0:x c1:min01 c2:max01 c3:min23 c4:max23
// TILE_M=128, 256 thr, 2 CTAs/SM (48KB smem). Uniform warps:
// producer warp owns 16 edges; consumer m32 x n32 (4m x 2n).
// 3-buffer ring, 5 phases. Gather phases: both load half-batches issued up
// front, mma_half slotted between issue and use (L2-resident XH: ~250cyc).
__global__ void __launch_bounds__(NTHREADS, 2)
meshconv_kernel(const int* __restrict__ nbr, const float* __restrict__ bias,
                float* __restrict__ out) {
    extern __shared__ char smem[];
    const uint32_t sb = smem_u32(smem);
    const int tid = threadIdx.x;
    const int lid = tid & 31, wid = tid >> 5;
    // consumer identity
    const int wm = wid & 3, wn = wid >> 2;
    const int g = lid >> 2, tig = lid & 3;
    // producer identity
    const int eo = lid >> 3, cs = lid & 7;
    const int we0 = wid * 16;

    // bias fragment (accumulator init values)
    float bv[4][2];
#pragma unroll
    for (int nf = 0; nf < 4; nf++) {
        int bc = wn * 32 + nf * 8 + tig * 2;
        bv[nf][0] = __ldg(bias + bc);
        bv[nf][1] = __ldg(bias + bc + 1);
    }

    const uint4* wrbase = WrepH + wn * 256 + lid;   // + c*512 per chunk

    // ---- prologue: NB + stage c0 of first tile into buf 0 ----
    int tile = blockIdx.x;
    int NBx, NBy, NBz, NBw;
    {
        int e = tile * TILE_M + we0 + (lid & 15);
        if (e > E_TOTAL - 1) e = E_TOTAL - 1;
        int4 v = __ldg((const int4*)nbr + e);
        NBx = v.x; NBy = v.y; NBz = v.z; NBw = v.w;
    }
    {
        uint4 V[4];
        x_load4(tile * TILE_M + we0, eo, cs, V);
        sts_stream(sb, we0, eo, cs, V);
    }
    __syncthreads();

    int bc3 = 0;   // buffer rotation: buf(j) = (bc3 + j) % 3
    for (; tile < NTILES; tile += gridDim.x) {
        int tn = tile + gridDim.x;
        if (tn >= NTILES) tn = tile;
        const int nbase = tn * TILE_M + we0;
        const int tbase = tile * TILE_M;

        const int u1 = (bc3 + 1 == 3) ? 0 : bc3 + 1;
        const int u2 = (u1 + 1 == 3) ? 0 : u1 + 1;
        const uint32_t b_c0 = sb + (uint32_t)bc3 * 16384u;   // c0, c3
        const uint32_t b_c1 = sb + (uint32_t)u1 * 16384u;    // c1, c4
        const uint32_t b_c2 = sb + (uint32_t)u2 * 16384u;    // c2, next c0

        float acc[2][4][4];
#pragma unroll
        for (int mb = 0; mb < 2; mb++)
#pragma unroll
            for (int nf = 0; nf < 4; nf++) {
                acc[mb][nf][0] = bv[nf][0];
                acc[mb][nf][1] = bv[nf][1];
                acc[mb][nf][2] = bv[nf][0];
                acc[mb][nf][3] = bv[nf][1];
            }

        uint4 MX[4];            // held max stream (16 regs)
        uint4 VA[2], VB[2], VA2[2], VB2[2];

        // ---- s0: pair0 (all loads first) + mma c0(b_c0); min01 -> b_c1
        pair_load2(NBx, NBy, 0, eo, cs, VA, VB);
        pair_load2(NBx, NBy, 2, eo, cs, VA2, VB2);
        mma_half(b_c0, wrbase + 0 * 512, wm, lid, 0, acc);
        pair_proc2(b_c1, we0, 0, eo, cs, VA, VB, MX);
        mma_half(b_c0, wrbase + 0 * 512, wm, lid, 1, acc);
        pair_proc2(b_c1, we0, 2, eo, cs, VA2, VB2, MX);
        __syncthreads();

        // ---- s1: STS max01 -> b_c2; pair1 + mma c1(b_c1); min23 -> b_c0
        sts_stream(b_c2, we0, eo, cs, MX);
        pair_load2(NBz, NBw, 0, eo, cs, VA, VB);
        pair_load2(NBz, NBw, 2, eo, cs, VA2, VB2);
        mma_half(b_c1, wrbase + 1 * 512, wm, lid, 0, acc);
        pair_proc2(b_c0, we0, 0, eo, cs, VA, VB, MX);
        mma_half(b_c1, wrbase + 1 * 512, wm, lid, 1, acc);
        pair_proc2(b_c0, we0, 2, eo, cs, VA2, VB2, MX);
        __syncthreads();

        // ---- s2: STS max23 -> b_c1; prefetch next NB; mma c2(b_c2)
        sts_stream(b_c1, we0, eo, cs, MX);
        int NBnx, NBny, NBnz, NBnw;
        {
            int e = nbase + (lid & 15);
            if (e > E_TOTAL - 1) e = E_TOTAL - 1;
            int4 v = __ldg((const int4*)nbr + e);
            NBnx = v.x; NBny = v.y; NBnz = v.z; NBnw = v.w;
        }
        mma_half(b_c2, wrbase + 2 * 512, wm, lid, 0, acc);
        mma_half(b_c2, wrbase + 2 * 512, wm, lid, 1, acc);
        __syncthreads();

        // ---- s3: next tile's c0 stream + mma c3(b_c0); STS -> b_c2
        {
            uint4 V[4];
            x_load4(nbase, eo, cs, V);
            mma_half(b_c0, wrbase + 3 * 512, wm, lid, 0, acc);
            sts_stream(b_c2, we0, eo, cs, V);
            mma_half(b_c0, wrbase + 3 * 512, wm, lid, 1, acc);
        }
        __syncthreads();

        // ---- s4: mma c4(b_c1); rotate; epilogue (pure STG -> no sync)
        mma_half(b_c1, wrbase + 4 * 512, wm, lid, 0, acc);
        mma_half(b_c1, wrbase + 4 * 512, wm, lid, 1, acc);
        NBx = NBnx; NBy = NBny; NBz = NBnz; NBw = NBnw;
        bc3 = u2;

#pragma unroll
        for (int mb = 0; mb < 2; mb++) {
#pragma unroll
            for (int nf = 0; nf < 4; nf++) {
                const int e0  = tbase + wm * 32 + mb * 16 + g;
                const int e1  = e0 + 8;
                const int col = wn * 32 + nf * 8 + tig * 2;
                if (e0 < E_TOTAL)
                    *(float2*)(out + (size_t)e0 * 64 + col) =
                        make_float2(acc[mb][nf][0], acc[mb][nf][1]);
                if (e1 < E_TOTAL)
                    *(float2*)(out + (size_t)e1 * 64 + col) =
                        make_float2(acc[mb][nf][2], acc[mb][nf][3]);
            }
        }
    }
}

// ---------------- launch ----------------
extern "C" void kernel_launch(void* const* d_in, const int* in_sizes, int n_in,
                              void* d_out, int out_size) {
    const float* x   = (const float*)d_in[0];
    const int*   nbr = (const int*)d_in[1];
    const float* W   = (const float*)d_in[2];
    const float* b   = (const float*)d_in[3];
    float* out = (float*)d_out;

    int nsm = 0;
    cudaDeviceGetAttribute(&nsm, cudaDevAttrMultiProcessorCount, 0);
    if (nsm <= 0) nsm = 148;

    convert_x_kernel<<<(E_TOTAL * 8 + 255) / 256, 256>>>((const float4*)x);
    repack_w_h<<<10, 256>>>(W);

    cudaFuncSetAttribute(meshconv_kernel,
                         cudaFuncAttributeMaxDynamicSharedMemorySize, SMEM_TOTAL);
    meshconv_kernel<<<2 * nsm, NTHREADS, SMEM_TOTAL>>>(nbr, b, out);
}